// round 12
// baseline (speedup 1.0000x reference)
#include <cuda_runtime.h>
#include <cuda_bf16.h>
#include <cstdint>
#include <math.h>

#define TOKENS 16384
#define D_IN   2048
#define D_HID  1024
#define N_EXP  64
#define TOPK   8
#define SLOPE  0.01f
#define KSPLIT1 512   // GEMM1: 4 panels of 512, sequential folds (FROZEN)
#define KSPLIT2 256   // GEMM2: 4 panels of 256, pairwise-tree fold (FROZEN)

// Scratch for hidden activations H [TOKENS, D_HID] (64 MB)
__device__ float g_H[(size_t)TOKENS * D_HID];

// ---------------------------------------------------------------------------
// GEMM1: H = leaky_relu(X @ W1^T + b1)
// NUMERICS (frozen): per element, 4 panels of 512; ascending FMA chain within
// a panel; panels folded sequentially. Schedule: register-staged prefetch
// software pipeline (load tile t+1 into regs while computing tile t).
// 128x128 tile, BK=16, 256 threads, 8x8 microtile.
// ---------------------------------------------------------------------------
#define BM 128
#define BN 128
#define BK 16
#define TM 8
#define TN 8
#define NT1 (D_IN / BK)   // 128 k-tiles

__global__ __launch_bounds__(256)
void gemm1_kernel(const float* __restrict__ X,
                  const float* __restrict__ W1,
                  const float* __restrict__ b1)
{
    __shared__ float As[BK][BM];
    __shared__ float Bs[BK][BN];

    const int block_m = blockIdx.y * BM;
    const int block_n = blockIdx.x * BN;
    const int tid  = threadIdx.x;
    const int trow = tid / 16;
    const int tcol = tid % 16;

    // Per-thread load coordinates (2 float4 per array per tile)
    const int r0 = tid >> 2;               // 0..63
    const int r1 = (tid + 256) >> 2;       // 64..127
    const int c0 = (tid & 3) * 4;          // 0,4,8,12

    const float* Xp0 = X  + (size_t)(block_m + r0) * D_IN + c0;
    const float* Xp1 = X  + (size_t)(block_m + r1) * D_IN + c0;
    const float* Wp0 = W1 + (size_t)(block_n + r0) * D_IN + c0;
    const float* Wp1 = W1 + (size_t)(block_n + r1) * D_IN + c0;

    float acc[TM][TN], tot[TM][TN];
    #pragma unroll
    for (int i = 0; i < TM; i++)
        #pragma unroll
        for (int j = 0; j < TN; j++) { acc[i][j] = 0.f; tot[i][j] = 0.f; }

    // Prologue: load tile 0 and store to smem
    float4 sx0 = *(const float4*)(Xp0);
    float4 sx1 = *(const float4*)(Xp1);
    float4 sw0 = *(const float4*)(Wp0);
    float4 sw1 = *(const float4*)(Wp1);

    As[c0 + 0][r0] = sx0.x; As[c0 + 1][r0] = sx0.y; As[c0 + 2][r0] = sx0.z; As[c0 + 3][r0] = sx0.w;
    As[c0 + 0][r1] = sx1.x; As[c0 + 1][r1] = sx1.y; As[c0 + 2][r1] = sx1.z; As[c0 + 3][r1] = sx1.w;
    Bs[c0 + 0][r0] = sw0.x; Bs[c0 + 1][r0] = sw0.y; Bs[c0 + 2][r0] = sw0.z; Bs[c0 + 3][r0] = sw0.w;
    Bs[c0 + 0][r1] = sw1.x; Bs[c0 + 1][r1] = sw1.y; Bs[c0 + 2][r1] = sw1.z; Bs[c0 + 3][r1] = sw1.w;
    __syncthreads();

    for (int t = 0; t < NT1; t++) {
        // Prefetch next tile into registers (overlaps with compute below)
        if (t + 1 < NT1) {
            int koff = (t + 1) * BK;
            sx0 = *(const float4*)(Xp0 + koff);
            sx1 = *(const float4*)(Xp1 + koff);
            sw0 = *(const float4*)(Wp0 + koff);
            sw1 = *(const float4*)(Wp1 + koff);
        }

        // Compute current tile (ascending k within tile — frozen ordering)
        #pragma unroll
        for (int k = 0; k < BK; k++) {
            float a[TM], b[TN];
            float4 a0 = *(const float4*)&As[k][trow * TM];
            float4 a1 = *(const float4*)&As[k][trow * TM + 4];
            a[0]=a0.x; a[1]=a0.y; a[2]=a0.z; a[3]=a0.w;
            a[4]=a1.x; a[5]=a1.y; a[6]=a1.z; a[7]=a1.w;
            float4 b0 = *(const float4*)&Bs[k][tcol * TN];
            float4 b1v= *(const float4*)&Bs[k][tcol * TN + 4];
            b[0]=b0.x; b[1]=b0.y; b[2]=b0.z; b[3]=b0.w;
            b[4]=b1v.x; b[5]=b1v.y; b[6]=b1v.z; b[7]=b1v.w;
            #pragma unroll
            for (int i = 0; i < TM; i++)
                #pragma unroll
                for (int j = 0; j < TN; j++)
                    acc[i][j] = fmaf(a[i], b[j], acc[i][j]);
        }

        // Sequential panel fold at 512 boundaries (frozen ordering)
        if ((((t + 1) * BK) % KSPLIT1) == 0) {
            #pragma unroll
            for (int i = 0; i < TM; i++)
                #pragma unroll
                for (int j = 0; j < TN; j++) {
                    tot[i][j] += acc[i][j];
                    acc[i][j] = 0.f;
                }
        }

        // Publish prefetched tile to smem
        if (t + 1 < NT1) {
            __syncthreads();   // everyone done reading current tile
            As[c0 + 0][r0] = sx0.x; As[c0 + 1][r0] = sx0.y; As[c0 + 2][r0] = sx0.z; As[c0 + 3][r0] = sx0.w;
            As[c0 + 0][r1] = sx1.x; As[c0 + 1][r1] = sx1.y; As[c0 + 2][r1] = sx1.z; As[c0 + 3][r1] = sx1.w;
            Bs[c0 + 0][r0] = sw0.x; Bs[c0 + 1][r0] = sw0.y; Bs[c0 + 2][r0] = sw0.z; Bs[c0 + 3][r0] = sw0.w;
            Bs[c0 + 0][r1] = sw1.x; Bs[c0 + 1][r1] = sw1.y; Bs[c0 + 2][r1] = sw1.z; Bs[c0 + 3][r1] = sw1.w;
            __syncthreads();
        }
    }

    #pragma unroll
    for (int i = 0; i < TM; i++) {
        int m = block_m + trow * TM + i;
        #pragma unroll
        for (int j4 = 0; j4 < TN; j4 += 4) {
            int n = block_n + tcol * TN + j4;
            float4 o;
            float v0 = tot[i][j4+0] + b1[n+0];
            float v1 = tot[i][j4+1] + b1[n+1];
            float v2 = tot[i][j4+2] + b1[n+2];
            float v3 = tot[i][j4+3] + b1[n+3];
            o.x = v0 >= 0.f ? v0 : SLOPE * v0;
            o.y = v1 >= 0.f ? v1 : SLOPE * v1;
            o.z = v2 >= 0.f ? v2 : SLOPE * v2;
            o.w = v3 >= 0.f ? v3 : SLOPE * v3;
            *(float4*)(g_H + (size_t)m * D_HID + n) = o;
        }
    }
}

// ---------------------------------------------------------------------------
// GEMM2: logits = H @ W2^T + b2.
// NUMERICS (frozen): 4 panels of 256 ascending chains, pairwise tree
// (p0+p1)+(p2+p3). Schedule: register-staged prefetch pipeline.
// Fused top-8 + softmax. 64 tokens x 64 experts per block, 256 threads.
// ---------------------------------------------------------------------------
#define K2CHUNK 32
#define NT2 (D_HID / K2CHUNK)   // 32 k-tiles

__global__ __launch_bounds__(256)
void gemm2_topk_kernel(const float* __restrict__ W2,
                       const float* __restrict__ b2,
                       float* __restrict__ out,
                       int out_size)
{
    __shared__ float Hs[K2CHUNK][64];
    __shared__ float Ws[K2CHUNK][64];
    __shared__ float ls[64][N_EXP + 1];

    const int tok0 = blockIdx.x * 64;
    const int tid  = threadIdx.x;
    const int ttok = (tid / 16) * 4;
    const int texp = (tid % 16) * 4;

    // Load coords: 2 float4 per array per tile
    const int r0 = tid >> 3;               // 0..31
    const int r1 = (tid + 256) >> 3;       // 32..63
    const int c0 = (tid & 7) * 4;          // 0..28

    const float* Hp0 = g_H + (size_t)(tok0 + r0) * D_HID + c0;
    const float* Hp1 = g_H + (size_t)(tok0 + r1) * D_HID + c0;
    const float* Wp0 = W2  + (size_t)r0 * D_HID + c0;
    const float* Wp1 = W2  + (size_t)r1 * D_HID + c0;

    float acc[4][4];
    float pan[4][4][4];
    #pragma unroll
    for (int i = 0; i < 4; i++)
        #pragma unroll
        for (int j = 0; j < 4; j++) {
            acc[i][j] = 0.f;
            #pragma unroll
            for (int p = 0; p < 4; p++) pan[p][i][j] = 0.f;
        }

    // Prologue: tile 0
    float4 sh0 = *(const float4*)(Hp0);
    float4 sh1 = *(const float4*)(Hp1);
    float4 sw0 = *(const float4*)(Wp0);
    float4 sw1 = *(const float4*)(Wp1);
    Hs[c0 + 0][r0] = sh0.x; Hs[c0 + 1][r0] = sh0.y; Hs[c0 + 2][r0] = sh0.z; Hs[c0 + 3][r0] = sh0.w;
    Hs[c0 + 0][r1] = sh1.x; Hs[c0 + 1][r1] = sh1.y; Hs[c0 + 2][r1] = sh1.z; Hs[c0 + 3][r1] = sh1.w;
    Ws[c0 + 0][r0] = sw0.x; Ws[c0 + 1][r0] = sw0.y; Ws[c0 + 2][r0] = sw0.z; Ws[c0 + 3][r0] = sw0.w;
    Ws[c0 + 0][r1] = sw1.x; Ws[c0 + 1][r1] = sw1.y; Ws[c0 + 2][r1] = sw1.z; Ws[c0 + 3][r1] = sw1.w;
    __syncthreads();

    int panel = 0;
    for (int t = 0; t < NT2; t++) {
        if (t + 1 < NT2) {
            int koff = (t + 1) * K2CHUNK;
            sh0 = *(const float4*)(Hp0 + koff);
            sh1 = *(const float4*)(Hp1 + koff);
            sw0 = *(const float4*)(Wp0 + koff);
            sw1 = *(const float4*)(Wp1 + koff);
        }

        #pragma unroll
        for (int k = 0; k < K2CHUNK; k++) {
            float4 a = *(const float4*)&Hs[k][ttok];
            float4 b = *(const float4*)&Ws[k][texp];
            float av[4] = {a.x, a.y, a.z, a.w};
            float bv[4] = {b.x, b.y, b.z, b.w};
            #pragma unroll
            for (int i = 0; i < 4; i++)
                #pragma unroll
                for (int j = 0; j < 4; j++)
                    acc[i][j] = fmaf(av[i], bv[j], acc[i][j]);
        }

        if ((((t + 1) * K2CHUNK) % KSPLIT2) == 0) {   // stash panel (frozen)
            #pragma unroll
            for (int i = 0; i < 4; i++)
                #pragma unroll
                for (int j = 0; j < 4; j++) {
                    pan[panel][i][j] = acc[i][j];
                    acc[i][j] = 0.f;
                }
            panel++;
        }

        if (t + 1 < NT2) {
            __syncthreads();
            Hs[c0 + 0][r0] = sh0.x; Hs[c0 + 1][r0] = sh0.y; Hs[c0 + 2][r0] = sh0.z; Hs[c0 + 3][r0] = sh0.w;
            Hs[c0 + 0][r1] = sh1.x; Hs[c0 + 1][r1] = sh1.y; Hs[c0 + 2][r1] = sh1.z; Hs[c0 + 3][r1] = sh1.w;
            Ws[c0 + 0][r0] = sw0.x; Ws[c0 + 1][r0] = sw0.y; Ws[c0 + 2][r0] = sw0.z; Ws[c0 + 3][r0] = sw0.w;
            Ws[c0 + 0][r1] = sw1.x; Ws[c0 + 1][r1] = sw1.y; Ws[c0 + 2][r1] = sw1.z; Ws[c0 + 3][r1] = sw1.w;
            __syncthreads();
        }
    }

    // Pairwise-tree combine + bias (frozen)
    #pragma unroll
    for (int i = 0; i < 4; i++)
        #pragma unroll
        for (int j = 0; j < 4; j++) {
            float lo = pan[0][i][j] + pan[1][i][j];
            float hi = pan[2][i][j] + pan[3][i][j];
            ls[ttok + i][texp + j] = (lo + hi) + b2[texp + j];
        }
    __syncthreads();

    // Top-8 + softmax (frozen semantics)
    if (tid < 64) {
        const int t = tid;
        float vals[TOPK];
        int   idxs[TOPK];
        uint64_t taken = 0ull;
        #pragma unroll
        for (int j = 0; j < TOPK; j++) {
            float best = -3.4e38f;
            int bi = 0;
            for (int e = 0; e < N_EXP; e++) {
                bool free_ = !((taken >> e) & 1ull);
                float v = ls[t][e];
                if (free_ && v > best) { best = v; bi = e; }
            }
            taken |= (1ull << bi);
            vals[j] = best;
            idxs[j] = bi;
        }
        double m = (double)vals[0];
        double e8[TOPK];
        double s = 0.0;
        #pragma unroll
        for (int j = 0; j < TOPK; j++) { e8[j] = exp((double)vals[j] - m); s += e8[j]; }
        const int gt = tok0 + t;
        #pragma unroll
        for (int j = 0; j < TOPK; j++)
            out[(size_t)gt * TOPK + j] = (float)(e8[j] / s);
        if (out_size >= 2 * TOKENS * TOPK) {
            float* oid = out + (size_t)TOKENS * TOPK;
            #pragma unroll
            for (int j = 0; j < TOPK; j++)
                oid[(size_t)gt * TOPK + j] = (float)idxs[j];
        }
    }
}

// ---------------------------------------------------------------------------
extern "C" void kernel_launch(void* const* d_in, const int* in_sizes, int n_in,
                              void* d_out, int out_size)
{
    const float* X  = (const float*)d_in[0];
    const float* W1 = (const float*)d_in[1];
    const float* b1 = (const float*)d_in[2];
    const float* W2 = (const float*)d_in[3];
    const float* b2 = (const float*)d_in[4];
    float* out = (float*)d_out;

    dim3 g1(D_HID / BN, TOKENS / BM);   // (8, 128)
    gemm1_kernel<<<g1, 256>>>(X, W1, b1);

    gemm2_topk_kernel<<<TOKENS / 64, 256>>>(W2, b2, out, out_size);
}

// round 13
// speedup vs baseline: 1.3855x; 1.3855x over previous
#include <cuda_runtime.h>
#include <cuda_bf16.h>
#include <cstdint>
#include <math.h>

#define TOKENS 16384
#define D_IN   2048
#define D_HID  1024
#define N_EXP  64
#define TOPK   8
#define SLOPE  0.01f
#define KSPLIT1 512   // GEMM1: 4 panels of 512, sequential folds (FROZEN)
#define KSPLIT2 256   // GEMM2: 4 panels of 256, pairwise-tree fold (FROZEN)

// Scratch for hidden activations H [TOKENS, D_HID] (64 MB)
__device__ float g_H[(size_t)TOKENS * D_HID];

// ---- cp.async helpers (gmem -> smem, no register staging) ------------------
__device__ __forceinline__ void cp4(uint32_t dst_smem, const float* src) {
    asm volatile("cp.async.ca.shared.global [%0], [%1], 4;\n"
                 :: "r"(dst_smem), "l"(src));
}
__device__ __forceinline__ void cp_commit() {
    asm volatile("cp.async.commit_group;\n");
}
__device__ __forceinline__ void cp_wait0() {
    asm volatile("cp.async.wait_group 0;\n");
}

// ---------------------------------------------------------------------------
// GEMM1: H = leaky_relu(X @ W1^T + b1)
// NUMERICS (frozen): 4 panels of 512; ascending FMA chain within panel;
// sequential panel folds. Schedule: cp.async DOUBLE-BUFFERED smem pipeline
// (no staging registers), one __syncthreads per k-tile.
// 128x128 tile, BK=16, 256 threads, 8x8 microtile.
// ---------------------------------------------------------------------------
#define BM 128
#define BN 128
#define BK 16
#define TM 8
#define TN 8
#define NT1 (D_IN / BK)   // 128 k-tiles

__global__ __launch_bounds__(256)
void gemm1_kernel(const float* __restrict__ X,
                  const float* __restrict__ W1,
                  const float* __restrict__ b1)
{
    __shared__ float As[2][BK][BM];
    __shared__ float Bs[2][BK][BN];

    const int block_m = blockIdx.y * BM;
    const int block_n = blockIdx.x * BN;
    const int tid  = threadIdx.x;
    const int trow = tid / 16;
    const int tcol = tid % 16;

    const uint32_t sA = (uint32_t)__cvta_generic_to_shared(&As[0][0][0]);
    const uint32_t sB = (uint32_t)__cvta_generic_to_shared(&Bs[0][0][0]);

    float acc[TM][TN], tot[TM][TN];
    #pragma unroll
    for (int i = 0; i < TM; i++)
        #pragma unroll
        for (int j = 0; j < TN; j++) { acc[i][j] = 0.f; tot[i][j] = 0.f; }

    // Issue tile t into buffer buf (transposing 4B copies: gmem [row][k] -> smem [k][row])
    auto issue1 = [&](int t, int buf) {
        const int k0 = t * BK;
        #pragma unroll
        for (int j = 0; j < 8; j++) {
            int idx = tid + j * 256;            // 0..2047
            int row = idx >> 4;                 // 0..127
            int kk  = idx & 15;                 // 0..15
            uint32_t off = (uint32_t)(((buf * BK + kk) * BM + row) * 4);
            cp4(sA + off, X  + (size_t)(block_m + row) * D_IN + k0 + kk);
            cp4(sB + off, W1 + (size_t)(block_n + row) * D_IN + k0 + kk);
        }
        cp_commit();
    };

    issue1(0, 0);

    for (int t = 0; t < NT1; t++) {
        cp_wait0();          // tile t landed in smem
        __syncthreads();     // all threads see it; prior compute done -> alt buffer free
        if (t + 1 < NT1) issue1(t + 1, (t + 1) & 1);

        const int buf = t & 1;
        #pragma unroll
        for (int k = 0; k < BK; k++) {
            float a[TM], b[TN];
            float4 a0 = *(const float4*)&As[buf][k][trow * TM];
            float4 a1 = *(const float4*)&As[buf][k][trow * TM + 4];
            a[0]=a0.x; a[1]=a0.y; a[2]=a0.z; a[3]=a0.w;
            a[4]=a1.x; a[5]=a1.y; a[6]=a1.z; a[7]=a1.w;
            float4 b0 = *(const float4*)&Bs[buf][k][tcol * TN];
            float4 b1v= *(const float4*)&Bs[buf][k][tcol * TN + 4];
            b[0]=b0.x; b[1]=b0.y; b[2]=b0.z; b[3]=b0.w;
            b[4]=b1v.x; b[5]=b1v.y; b[6]=b1v.z; b[7]=b1v.w;
            #pragma unroll
            for (int i = 0; i < TM; i++)
                #pragma unroll
                for (int j = 0; j < TN; j++)
                    acc[i][j] = fmaf(a[i], b[j], acc[i][j]);
        }

        if ((((t + 1) * BK) % KSPLIT1) == 0) {   // sequential panel fold (frozen)
            #pragma unroll
            for (int i = 0; i < TM; i++)
                #pragma unroll
                for (int j = 0; j < TN; j++) {
                    tot[i][j] += acc[i][j];
                    acc[i][j] = 0.f;
                }
        }
    }

    #pragma unroll
    for (int i = 0; i < TM; i++) {
        int m = block_m + trow * TM + i;
        #pragma unroll
        for (int j4 = 0; j4 < TN; j4 += 4) {
            int n = block_n + tcol * TN + j4;
            float4 o;
            float v0 = tot[i][j4+0] + b1[n+0];
            float v1 = tot[i][j4+1] + b1[n+1];
            float v2 = tot[i][j4+2] + b1[n+2];
            float v3 = tot[i][j4+3] + b1[n+3];
            o.x = v0 >= 0.f ? v0 : SLOPE * v0;
            o.y = v1 >= 0.f ? v1 : SLOPE * v1;
            o.z = v2 >= 0.f ? v2 : SLOPE * v2;
            o.w = v3 >= 0.f ? v3 : SLOPE * v3;
            *(float4*)(g_H + (size_t)m * D_HID + n) = o;
        }
    }
}

// ---------------------------------------------------------------------------
// GEMM2: logits = H @ W2^T + b2.  (R11-passing version, verbatim numerics)
// 4 panels of 256 ascending chains, pairwise tree (p0+p1)+(p2+p3).
// Fused top-8 + softmax. 64 tokens x 64 experts per block, 256 threads.
// ---------------------------------------------------------------------------
#define K2CHUNK 32

__global__ __launch_bounds__(256)
void gemm2_topk_kernel(const float* __restrict__ W2,
                       const float* __restrict__ b2,
                       float* __restrict__ out,
                       int out_size)
{
    __shared__ float Hs[K2CHUNK][64];
    __shared__ float Ws[K2CHUNK][64];
    __shared__ float ls[64][N_EXP + 1];

    const int tok0 = blockIdx.x * 64;
    const int tid  = threadIdx.x;
    const int ttok = (tid / 16) * 4;
    const int texp = (tid % 16) * 4;

    float acc[4][4];
    float pan[4][4][4];
    #pragma unroll
    for (int i = 0; i < 4; i++)
        #pragma unroll
        for (int j = 0; j < 4; j++) {
            acc[i][j] = 0.f;
            #pragma unroll
            for (int p = 0; p < 4; p++) pan[p][i][j] = 0.f;
        }

    int panel = 0;
    for (int k0 = 0; k0 < D_HID; k0 += K2CHUNK) {
        #pragma unroll
        for (int j = 0; j < 2; j++) {
            int idx = tid + j * 256;
            int row = idx >> 3;
            int k4  = (idx & 7) * 4;
            float4 h = *(const float4*)(g_H + (size_t)(tok0 + row) * D_HID + k0 + k4);
            Hs[k4 + 0][row] = h.x; Hs[k4 + 1][row] = h.y;
            Hs[k4 + 2][row] = h.z; Hs[k4 + 3][row] = h.w;
            float4 w = *(const float4*)(W2 + (size_t)row * D_HID + k0 + k4);
            Ws[k4 + 0][row] = w.x; Ws[k4 + 1][row] = w.y;
            Ws[k4 + 2][row] = w.z; Ws[k4 + 3][row] = w.w;
        }
        __syncthreads();

        #pragma unroll
        for (int k = 0; k < K2CHUNK; k++) {
            float4 a = *(const float4*)&Hs[k][ttok];
            float4 b = *(const float4*)&Ws[k][texp];
            float av[4] = {a.x, a.y, a.z, a.w};
            float bv[4] = {b.x, b.y, b.z, b.w};
            #pragma unroll
            for (int i = 0; i < 4; i++)
                #pragma unroll
                for (int j = 0; j < 4; j++)
                    acc[i][j] = fmaf(av[i], bv[j], acc[i][j]);
        }
        __syncthreads();

        if (((k0 + K2CHUNK) % KSPLIT2) == 0) {   // stash panel (frozen)
            #pragma unroll
            for (int i = 0; i < 4; i++)
                #pragma unroll
                for (int j = 0; j < 4; j++) {
                    pan[panel][i][j] = acc[i][j];
                    acc[i][j] = 0.f;
                }
            panel++;
        }
    }

    // Pairwise-tree combine + bias (frozen)
    #pragma unroll
    for (int i = 0; i < 4; i++)
        #pragma unroll
        for (int j = 0; j < 4; j++) {
            float lo = pan[0][i][j] + pan[1][i][j];
            float hi = pan[2][i][j] + pan[3][i][j];
            ls[ttok + i][texp + j] = (lo + hi) + b2[texp + j];
        }
    __syncthreads();

    // Top-8 + softmax (frozen semantics)
    if (tid < 64) {
        const int t = tid;
        float vals[TOPK];
        int   idxs[TOPK];
        uint64_t taken = 0ull;
        #pragma unroll
        for (int j = 0; j < TOPK; j++) {
            float best = -3.4e38f;
            int bi = 0;
            for (int e = 0; e < N_EXP; e++) {
                bool free_ = !((taken >> e) & 1ull);
                float v = ls[t][e];
                if (free_ && v > best) { best = v; bi = e; }
            }
            taken |= (1ull << bi);
            vals[j] = best;
            idxs[j] = bi;
        }
        double m = (double)vals[0];
        double e8[TOPK];
        double s = 0.0;
        #pragma unroll
        for (int j = 0; j < TOPK; j++) { e8[j] = exp((double)vals[j] - m); s += e8[j]; }
        const int gt = tok0 + t;
        #pragma unroll
        for (int j = 0; j < TOPK; j++)
            out[(size_t)gt * TOPK + j] = (float)(e8[j] / s);
        if (out_size >= 2 * TOKENS * TOPK) {
            float* oid = out + (size_t)TOKENS * TOPK;
            #pragma unroll
            for (int j = 0; j < TOPK; j++)
                oid[(size_t)gt * TOPK + j] = (float)idxs[j];
        }
    }
}

// ---------------------------------------------------------------------------
extern "C" void kernel_launch(void* const* d_in, const int* in_sizes, int n_in,
                              void* d_out, int out_size)
{
    const float* X  = (const float*)d_in[0];
    const float* W1 = (const float*)d_in[1];
    const float* b1 = (const float*)d_in[2];
    const float* W2 = (const float*)d_in[3];
    const float* b2 = (const float*)d_in[4];
    float* out = (float*)d_out;

    dim3 g1(D_HID / BN, TOKENS / BM);   // (8, 128)
    gemm1_kernel<<<g1, 256>>>(X, W1, b1);

    gemm2_topk_kernel<<<TOKENS / 64, 256>>>(W2, b2, out, out_size);
}

// round 14
// speedup vs baseline: 1.7424x; 1.2576x over previous
#include <cuda_runtime.h>
#include <cuda_bf16.h>
#include <cstdint>
#include <math.h>

#define TOKENS 16384
#define D_IN   2048
#define D_HID  1024
#define N_EXP  64
#define TOPK   8
#define SLOPE  0.01f
#define KSPLIT1 512   // GEMM1: 4 panels of 512, sequential folds (FROZEN)
#define KSPLIT2 256   // GEMM2: 4 panels of 256, pairwise-tree fold (FROZEN)

// Scratch for hidden activations H [TOKENS, D_HID] (64 MB)
__device__ float g_H[(size_t)TOKENS * D_HID];

// ---- packed f32x2 helpers (each half rounds exactly like scalar fmaf/add) --
__device__ __forceinline__ uint64_t bcast2(float a) {
    uint64_t r;
    asm("mov.b64 %0, {%1, %1};" : "=l"(r) : "f"(a));
    return r;
}
__device__ __forceinline__ void fma2(uint64_t& d, uint64_t a, uint64_t b) {
    asm("fma.rn.f32x2 %0, %1, %2, %0;" : "+l"(d) : "l"(a), "l"(b));
}
__device__ __forceinline__ void add2(uint64_t& d, uint64_t a) {
    asm("add.rn.f32x2 %0, %0, %1;" : "+l"(d) : "l"(a));
}

// ---------------------------------------------------------------------------
// GEMM1: H = leaky_relu(X @ W1^T + b1)
// NUMERICS (frozen): 4 panels of 512; per-element ascending FMA chain within
// panel; sequential panel folds. Arithmetic: packed f32x2 along the
// n-direction — acc pair (j, j+1) in one 64-bit reg, a[i] broadcast; each
// half rounds identically to scalar fmaf => bitwise-identical logits.
// 128x128 tile, BK=16, 256 threads, 8x8 microtile. R11 load schedule.
// ---------------------------------------------------------------------------
#define BM 128
#define BN 128
#define BK 16
#define TM 8
#define TN 8

__global__ __launch_bounds__(256)
void gemm1_kernel(const float* __restrict__ X,
                  const float* __restrict__ W1,
                  const float* __restrict__ b1)
{
    __shared__ float As[BK][BM];
    __shared__ float Bs[BK][BN];

    const int block_m = blockIdx.y * BM;
    const int block_n = blockIdx.x * BN;
    const int tid  = threadIdx.x;
    const int trow = tid / 16;
    const int tcol = tid % 16;

    // acc/tot packed: [i][jp] holds outputs (j=2*jp, j=2*jp+1)
    uint64_t accP[TM][TN / 2], totP[TM][TN / 2];
    const uint64_t z2 = 0ull;   // (0.f, 0.f)
    #pragma unroll
    for (int i = 0; i < TM; i++)
        #pragma unroll
        for (int jp = 0; jp < TN / 2; jp++) { accP[i][jp] = z2; totP[i][jp] = z2; }

    for (int k0 = 0; k0 < D_IN; k0 += BK) {
        #pragma unroll
        for (int j = 0; j < 2; j++) {
            int idx = tid + j * 256;
            int row = idx >> 2;
            int k4  = (idx & 3) * 4;
            float4 v = *(const float4*)(X  + (size_t)(block_m + row) * D_IN + k0 + k4);
            As[k4 + 0][row] = v.x; As[k4 + 1][row] = v.y;
            As[k4 + 2][row] = v.z; As[k4 + 3][row] = v.w;
            float4 w = *(const float4*)(W1 + (size_t)(block_n + row) * D_IN + k0 + k4);
            Bs[k4 + 0][row] = w.x; Bs[k4 + 1][row] = w.y;
            Bs[k4 + 2][row] = w.z; Bs[k4 + 3][row] = w.w;
        }
        __syncthreads();

        #pragma unroll
        for (int k = 0; k < BK; k++) {
            float a[TM];
            float4 a0 = *(const float4*)&As[k][trow * TM];
            float4 a1 = *(const float4*)&As[k][trow * TM + 4];
            a[0]=a0.x; a[1]=a0.y; a[2]=a0.z; a[3]=a0.w;
            a[4]=a1.x; a[5]=a1.y; a[6]=a1.z; a[7]=a1.w;

            // b pairs: 4 packed u64 covering n = tcol*8 .. tcol*8+7
            float4 b0 = *(const float4*)&Bs[k][tcol * TN];
            float4 b1v= *(const float4*)&Bs[k][tcol * TN + 4];
            uint64_t bP[4];
            bP[0] = *(const uint64_t*)&b0.x;   // (b0.x, b0.y)
            bP[1] = *(const uint64_t*)&b0.z;   // (b0.z, b0.w)
            bP[2] = *(const uint64_t*)&b1v.x;
            bP[3] = *(const uint64_t*)&b1v.z;

            #pragma unroll
            for (int i = 0; i < TM; i++) {
                uint64_t aa = bcast2(a[i]);
                #pragma unroll
                for (int jp = 0; jp < TN / 2; jp++)
                    fma2(accP[i][jp], aa, bP[jp]);
            }
        }
        __syncthreads();

        if (((k0 + BK) % KSPLIT1) == 0) {   // sequential panel fold (frozen)
            #pragma unroll
            for (int i = 0; i < TM; i++)
                #pragma unroll
                for (int jp = 0; jp < TN / 2; jp++) {
                    add2(totP[i][jp], accP[i][jp]);
                    accP[i][jp] = z2;
                }
        }
    }

    #pragma unroll
    for (int i = 0; i < TM; i++) {
        int m = block_m + trow * TM + i;
        #pragma unroll
        for (int jp4 = 0; jp4 < 2; jp4++) {     // two float4 stores
            int n = block_n + tcol * TN + jp4 * 4;
            float t0 = ((const float*)&totP[i][jp4 * 2 + 0])[0];
            float t1 = ((const float*)&totP[i][jp4 * 2 + 0])[1];
            float t2 = ((const float*)&totP[i][jp4 * 2 + 1])[0];
            float t3 = ((const float*)&totP[i][jp4 * 2 + 1])[1];
            float v0 = t0 + b1[n+0];
            float v1 = t1 + b1[n+1];
            float v2 = t2 + b1[n+2];
            float v3 = t3 + b1[n+3];
            float4 o;
            o.x = v0 >= 0.f ? v0 : SLOPE * v0;
            o.y = v1 >= 0.f ? v1 : SLOPE * v1;
            o.z = v2 >= 0.f ? v2 : SLOPE * v2;
            o.w = v3 >= 0.f ? v3 : SLOPE * v3;
            *(float4*)(g_H + (size_t)m * D_HID + n) = o;
        }
    }
}

// ---------------------------------------------------------------------------
// GEMM2: logits = H @ W2^T + b2.  (R11-passing version, verbatim)
// 4 panels of 256 ascending chains, pairwise tree (p0+p1)+(p2+p3).
// Fused top-8 + softmax. 64 tokens x 64 experts per block, 256 threads.
// ---------------------------------------------------------------------------
#define K2CHUNK 32

__global__ __launch_bounds__(256)
void gemm2_topk_kernel(const float* __restrict__ W2,
                       const float* __restrict__ b2,
                       float* __restrict__ out,
                       int out_size)
{
    __shared__ float Hs[K2CHUNK][64];
    __shared__ float Ws[K2CHUNK][64];
    __shared__ float ls[64][N_EXP + 1];

    const int tok0 = blockIdx.x * 64;
    const int tid  = threadIdx.x;
    const int ttok = (tid / 16) * 4;
    const int texp = (tid % 16) * 4;

    float acc[4][4];
    float pan[4][4][4];
    #pragma unroll
    for (int i = 0; i < 4; i++)
        #pragma unroll
        for (int j = 0; j < 4; j++) {
            acc[i][j] = 0.f;
            #pragma unroll
            for (int p = 0; p < 4; p++) pan[p][i][j] = 0.f;
        }

    int panel = 0;
    for (int k0 = 0; k0 < D_HID; k0 += K2CHUNK) {
        #pragma unroll
        for (int j = 0; j < 2; j++) {
            int idx = tid + j * 256;
            int row = idx >> 3;
            int k4  = (idx & 7) * 4;
            float4 h = *(const float4*)(g_H + (size_t)(tok0 + row) * D_HID + k0 + k4);
            Hs[k4 + 0][row] = h.x; Hs[k4 + 1][row] = h.y;
            Hs[k4 + 2][row] = h.z; Hs[k4 + 3][row] = h.w;
            float4 w = *(const float4*)(W2 + (size_t)row * D_HID + k0 + k4);
            Ws[k4 + 0][row] = w.x; Ws[k4 + 1][row] = w.y;
            Ws[k4 + 2][row] = w.z; Ws[k4 + 3][row] = w.w;
        }
        __syncthreads();

        #pragma unroll
        for (int k = 0; k < K2CHUNK; k++) {
            float4 a = *(const float4*)&Hs[k][ttok];
            float4 b = *(const float4*)&Ws[k][texp];
            float av[4] = {a.x, a.y, a.z, a.w};
            float bv[4] = {b.x, b.y, b.z, b.w};
            #pragma unroll
            for (int i = 0; i < 4; i++)
                #pragma unroll
                for (int j = 0; j < 4; j++)
                    acc[i][j] = fmaf(av[i], bv[j], acc[i][j]);
        }
        __syncthreads();

        if (((k0 + K2CHUNK) % KSPLIT2) == 0) {   // stash panel (frozen)
            #pragma unroll
            for (int i = 0; i < 4; i++)
                #pragma unroll
                for (int j = 0; j < 4; j++) {
                    pan[panel][i][j] = acc[i][j];
                    acc[i][j] = 0.f;
                }
            panel++;
        }
    }

    // Pairwise-tree combine + bias (frozen)
    #pragma unroll
    for (int i = 0; i < 4; i++)
        #pragma unroll
        for (int j = 0; j < 4; j++) {
            float lo = pan[0][i][j] + pan[1][i][j];
            float hi = pan[2][i][j] + pan[3][i][j];
            ls[ttok + i][texp + j] = (lo + hi) + b2[texp + j];
        }
    __syncthreads();

    // Top-8 + softmax (frozen semantics)
    if (tid < 64) {
        const int t = tid;
        float vals[TOPK];
        int   idxs[TOPK];
        uint64_t taken = 0ull;
        #pragma unroll
        for (int j = 0; j < TOPK; j++) {
            float best = -3.4e38f;
            int bi = 0;
            for (int e = 0; e < N_EXP; e++) {
                bool free_ = !((taken >> e) & 1ull);
                float v = ls[t][e];
                if (free_ && v > best) { best = v; bi = e; }
            }
            taken |= (1ull << bi);
            vals[j] = best;
            idxs[j] = bi;
        }
        double m = (double)vals[0];
        double e8[TOPK];
        double s = 0.0;
        #pragma unroll
        for (int j = 0; j < TOPK; j++) { e8[j] = exp((double)vals[j] - m); s += e8[j]; }
        const int gt = tok0 + t;
        #pragma unroll
        for (int j = 0; j < TOPK; j++)
            out[(size_t)gt * TOPK + j] = (float)(e8[j] / s);
        if (out_size >= 2 * TOKENS * TOPK) {
            float* oid = out + (size_t)TOKENS * TOPK;
            #pragma unroll
            for (int j = 0; j < TOPK; j++)
                oid[(size_t)gt * TOPK + j] = (float)idxs[j];
        }
    }
}

// ---------------------------------------------------------------------------
extern "C" void kernel_launch(void* const* d_in, const int* in_sizes, int n_in,
                              void* d_out, int out_size)
{
    const float* X  = (const float*)d_in[0];
    const float* W1 = (const float*)d_in[1];
    const float* b1 = (const float*)d_in[2];
    const float* W2 = (const float*)d_in[3];
    const float* b2 = (const float*)d_in[4];
    float* out = (float*)d_out;

    dim3 g1(D_HID / BN, TOKENS / BM);   // (8, 128)
    gemm1_kernel<<<g1, 256>>>(X, W1, b1);

    gemm2_topk_kernel<<<TOKENS / 64, 256>>>(W2, b2, out, out_size);
}

// round 15
// speedup vs baseline: 2.0385x; 1.1699x over previous
#include <cuda_runtime.h>
#include <cuda_bf16.h>
#include <cstdint>
#include <math.h>

#define TOKENS 16384
#define D_IN   2048
#define D_HID  1024
#define N_EXP  64
#define TOPK   8
#define SLOPE  0.01f
#define KSPLIT1 512   // GEMM1: 4 panels of 512, sequential folds (FROZEN)
#define KSPLIT2 256   // GEMM2: 4 panels of 256, pairwise-tree fold (FROZEN)

// Scratch for hidden activations H [TOKENS, D_HID] (64 MB)
__device__ float g_H[(size_t)TOKENS * D_HID];

// ---- packed f32x2 helpers (each half rounds exactly like scalar fmaf/add) --
__device__ __forceinline__ uint64_t bcast2(float a) {
    uint64_t r;
    asm("mov.b64 %0, {%1, %1};" : "=l"(r) : "f"(a));
    return r;
}
__device__ __forceinline__ void fma2(uint64_t& d, uint64_t a, uint64_t b) {
    asm("fma.rn.f32x2 %0, %1, %2, %0;" : "+l"(d) : "l"(a), "l"(b));
}
__device__ __forceinline__ void unpack2(float& lo, float& hi, uint64_t v) {
    asm("mov.b64 {%0, %1}, %2;" : "=f"(lo), "=f"(hi) : "l"(v));
}

// ---------------------------------------------------------------------------
// GEMM1: H = leaky_relu(X @ W1^T + b1)
// NUMERICS (frozen): 4 panels of 512; per-element ascending FMA chain within
// panel; sequential panel folds. Arithmetic: packed f32x2 (n-pairs).
// NEW schedule: tot lives in SMEM (touched only at 4 fold points + epilogue),
// freeing ~64 regs -> __launch_bounds__(256,2) -> 2 blocks/SM (16 warps)
// to hide sync/LDG latency. Dynamic smem: As + Bs + totS = 80KB/block.
// ---------------------------------------------------------------------------
#define BM 128
#define BN 128
#define BK 16
#define TM 8
#define TN 8

#define SM_AS    0                    // 16*128 floats
#define SM_BS    (BK * BM)            // 16*128 floats
#define SM_TOT   (2 * BK * BM)        // 64*256 floats
#define SM1_FLOATS (2 * BK * BM + 64 * 256)   // 20480 floats = 80KB

__global__ __launch_bounds__(256, 2)
void gemm1_kernel(const float* __restrict__ X,
                  const float* __restrict__ W1,
                  const float* __restrict__ b1)
{
    extern __shared__ float smemPool[];
    float* As   = smemPool + SM_AS;    // [k][m] : As[k*BM + m]
    float* Bs   = smemPool + SM_BS;    // [k][n]
    float* totS = smemPool + SM_TOT;   // [elem][tid] : totS[e*256 + tid]

    const int block_m = blockIdx.y * BM;
    const int block_n = blockIdx.x * BN;
    const int tid  = threadIdx.x;
    const int trow = tid / 16;
    const int tcol = tid % 16;

    // zero tot
    #pragma unroll
    for (int e = 0; e < 64; e++) totS[e * 256 + tid] = 0.f;

    uint64_t accP[TM][TN / 2];
    const uint64_t z2 = 0ull;
    #pragma unroll
    for (int i = 0; i < TM; i++)
        #pragma unroll
        for (int jp = 0; jp < TN / 2; jp++) accP[i][jp] = z2;

    for (int k0 = 0; k0 < D_IN; k0 += BK) {
        #pragma unroll
        for (int j = 0; j < 2; j++) {
            int idx = tid + j * 256;
            int row = idx >> 2;
            int k4  = (idx & 3) * 4;
            float4 v = *(const float4*)(X  + (size_t)(block_m + row) * D_IN + k0 + k4);
            As[(k4 + 0) * BM + row] = v.x; As[(k4 + 1) * BM + row] = v.y;
            As[(k4 + 2) * BM + row] = v.z; As[(k4 + 3) * BM + row] = v.w;
            float4 w = *(const float4*)(W1 + (size_t)(block_n + row) * D_IN + k0 + k4);
            Bs[(k4 + 0) * BM + row] = w.x; Bs[(k4 + 1) * BM + row] = w.y;
            Bs[(k4 + 2) * BM + row] = w.z; Bs[(k4 + 3) * BM + row] = w.w;
        }
        __syncthreads();

        #pragma unroll
        for (int k = 0; k < BK; k++) {
            float a[TM];
            float4 a0 = *(const float4*)&As[k * BM + trow * TM];
            float4 a1 = *(const float4*)&As[k * BM + trow * TM + 4];
            a[0]=a0.x; a[1]=a0.y; a[2]=a0.z; a[3]=a0.w;
            a[4]=a1.x; a[5]=a1.y; a[6]=a1.z; a[7]=a1.w;

            float4 b0 = *(const float4*)&Bs[k * BM + tcol * TN];
            float4 b1v= *(const float4*)&Bs[k * BM + tcol * TN + 4];
            uint64_t bP[4];
            bP[0] = *(const uint64_t*)&b0.x;
            bP[1] = *(const uint64_t*)&b0.z;
            bP[2] = *(const uint64_t*)&b1v.x;
            bP[3] = *(const uint64_t*)&b1v.z;

            #pragma unroll
            for (int i = 0; i < TM; i++) {
                uint64_t aa = bcast2(a[i]);
                #pragma unroll
                for (int jp = 0; jp < TN / 2; jp++)
                    fma2(accP[i][jp], aa, bP[jp]);
            }
        }
        __syncthreads();

        if (((k0 + BK) % KSPLIT1) == 0) {   // sequential panel fold (frozen)
            #pragma unroll
            for (int i = 0; i < TM; i++)
                #pragma unroll
                for (int jp = 0; jp < TN / 2; jp++) {
                    float lo, hi;
                    unpack2(lo, hi, accP[i][jp]);
                    int e = i * TN + jp * 2;
                    totS[e * 256 + tid]       += lo;
                    totS[(e + 1) * 256 + tid] += hi;
                    accP[i][jp] = z2;
                }
        }
    }

    #pragma unroll
    for (int i = 0; i < TM; i++) {
        int m = block_m + trow * TM + i;
        #pragma unroll
        for (int j4 = 0; j4 < TN; j4 += 4) {
            int n = block_n + tcol * TN + j4;
            int e = i * TN + j4;
            float v0 = totS[(e + 0) * 256 + tid] + b1[n+0];
            float v1 = totS[(e + 1) * 256 + tid] + b1[n+1];
            float v2 = totS[(e + 2) * 256 + tid] + b1[n+2];
            float v3 = totS[(e + 3) * 256 + tid] + b1[n+3];
            float4 o;
            o.x = v0 >= 0.f ? v0 : SLOPE * v0;
            o.y = v1 >= 0.f ? v1 : SLOPE * v1;
            o.z = v2 >= 0.f ? v2 : SLOPE * v2;
            o.w = v3 >= 0.f ? v3 : SLOPE * v3;
            *(float4*)(g_H + (size_t)m * D_HID + n) = o;
        }
    }
}

// ---------------------------------------------------------------------------
// GEMM2: logits = H @ W2^T + b2.  (R11-passing version, verbatim)
// 4 panels of 256 ascending chains, pairwise tree (p0+p1)+(p2+p3).
// Fused top-8 + softmax. 64 tokens x 64 experts per block, 256 threads.
// ---------------------------------------------------------------------------
#define K2CHUNK 32

__global__ __launch_bounds__(256)
void gemm2_topk_kernel(const float* __restrict__ W2,
                       const float* __restrict__ b2,
                       float* __restrict__ out,
                       int out_size)
{
    __shared__ float Hs[K2CHUNK][64];
    __shared__ float Ws[K2CHUNK][64];
    __shared__ float ls[64][N_EXP + 1];

    const int tok0 = blockIdx.x * 64;
    const int tid  = threadIdx.x;
    const int ttok = (tid / 16) * 4;
    const int texp = (tid % 16) * 4;

    float acc[4][4];
    float pan[4][4][4];
    #pragma unroll
    for (int i = 0; i < 4; i++)
        #pragma unroll
        for (int j = 0; j < 4; j++) {
            acc[i][j] = 0.f;
            #pragma unroll
            for (int p = 0; p < 4; p++) pan[p][i][j] = 0.f;
        }

    int panel = 0;
    for (int k0 = 0; k0 < D_HID; k0 += K2CHUNK) {
        #pragma unroll
        for (int j = 0; j < 2; j++) {
            int idx = tid + j * 256;
            int row = idx >> 3;
            int k4  = (idx & 7) * 4;
            float4 h = *(const float4*)(g_H + (size_t)(tok0 + row) * D_HID + k0 + k4);
            Hs[k4 + 0][row] = h.x; Hs[k4 + 1][row] = h.y;
            Hs[k4 + 2][row] = h.z; Hs[k4 + 3][row] = h.w;
            float4 w = *(const float4*)(W2 + (size_t)row * D_HID + k0 + k4);
            Ws[k4 + 0][row] = w.x; Ws[k4 + 1][row] = w.y;
            Ws[k4 + 2][row] = w.z; Ws[k4 + 3][row] = w.w;
        }
        __syncthreads();

        #pragma unroll
        for (int k = 0; k < K2CHUNK; k++) {
            float4 a = *(const float4*)&Hs[k][ttok];
            float4 b = *(const float4*)&Ws[k][texp];
            float av[4] = {a.x, a.y, a.z, a.w};
            float bv[4] = {b.x, b.y, b.z, b.w};
            #pragma unroll
            for (int i = 0; i < 4; i++)
                #pragma unroll
                for (int j = 0; j < 4; j++)
                    acc[i][j] = fmaf(av[i], bv[j], acc[i][j]);
        }
        __syncthreads();

        if (((k0 + K2CHUNK) % KSPLIT2) == 0) {   // stash panel (frozen)
            #pragma unroll
            for (int i = 0; i < 4; i++)
                #pragma unroll
                for (int j = 0; j < 4; j++) {
                    pan[panel][i][j] = acc[i][j];
                    acc[i][j] = 0.f;
                }
            panel++;
        }
    }

    // Pairwise-tree combine + bias (frozen)
    #pragma unroll
    for (int i = 0; i < 4; i++)
        #pragma unroll
        for (int j = 0; j < 4; j++) {
            float lo = pan[0][i][j] + pan[1][i][j];
            float hi = pan[2][i][j] + pan[3][i][j];
            ls[ttok + i][texp + j] = (lo + hi) + b2[texp + j];
        }
    __syncthreads();

    // Top-8 + softmax (frozen semantics)
    if (tid < 64) {
        const int t = tid;
        float vals[TOPK];
        int   idxs[TOPK];
        uint64_t taken = 0ull;
        #pragma unroll
        for (int j = 0; j < TOPK; j++) {
            float best = -3.4e38f;
            int bi = 0;
            for (int e = 0; e < N_EXP; e++) {
                bool free_ = !((taken >> e) & 1ull);
                float v = ls[t][e];
                if (free_ && v > best) { best = v; bi = e; }
            }
            taken |= (1ull << bi);
            vals[j] = best;
            idxs[j] = bi;
        }
        double m = (double)vals[0];
        double e8[TOPK];
        double s = 0.0;
        #pragma unroll
        for (int j = 0; j < TOPK; j++) { e8[j] = exp((double)vals[j] - m); s += e8[j]; }
        const int gt = tok0 + t;
        #pragma unroll
        for (int j = 0; j < TOPK; j++)
            out[(size_t)gt * TOPK + j] = (float)(e8[j] / s);
        if (out_size >= 2 * TOKENS * TOPK) {
            float* oid = out + (size_t)TOKENS * TOPK;
            #pragma unroll
            for (int j = 0; j < TOPK; j++)
                oid[(size_t)gt * TOPK + j] = (float)idxs[j];
        }
    }
}

// ---------------------------------------------------------------------------
extern "C" void kernel_launch(void* const* d_in, const int* in_sizes, int n_in,
                              void* d_out, int out_size)
{
    const float* X  = (const float*)d_in[0];
    const float* W1 = (const float*)d_in[1];
    const float* b1 = (const float*)d_in[2];
    const float* W2 = (const float*)d_in[3];
    const float* b2 = (const float*)d_in[4];
    float* out = (float*)d_out;

    // Dynamic smem for gemm1 (80KB > 48KB static limit)
    static int attr_set = 0;
    if (!attr_set) {
        cudaFuncSetAttribute(gemm1_kernel,
                             cudaFuncAttributeMaxDynamicSharedMemorySize,
                             SM1_FLOATS * (int)sizeof(float));
        attr_set = 1;
    }

    dim3 g1(D_HID / BN, TOKENS / BM);   // (8, 128)
    gemm1_kernel<<<g1, 256, SM1_FLOATS * sizeof(float)>>>(X, W1, b1);

    gemm2_topk_kernel<<<TOKENS / 64, 256>>>(W2, b2, out, out_size);
}